// round 6
// baseline (speedup 1.0000x reference)
#include <cuda_runtime.h>
#include <cstdint>

#define B_   256
#define T_   128
#define IN_  128
#define H_   256
#define H3_  768
#define OUT_ 128

#define ROWS 8        // (c,b) rows of state per persistent block
#define NBLK 96       // 768 / ROWS
#define PTH  256      // 8 warps: 2 per SMSP (balanced); thread j owns cols {j, j+256, j+512}
#define KC   32       // k-chunk rows of Wh per bulk copy
#define NCHUNK (H_/KC)             // 8
#define CHUNK_BYTES (KC*H3_*4)     // 98304
#define GX_BYTES (ROWS*H3_*4)      // 24576
#define HSTR 10                    // hst column stride (pad for bank spread + b64 align)
#define HST_FLOATS (H_*HSTR)       // 2560
#define BS_FLOATS  (2*KC*H3_)      // 49152
#define GXS_FLOATS (ROWS*H3_)      // 6144
#define SMEM_FLOATS (HST_FLOATS + BS_FLOATS + GXS_FLOATS)
#define SMEM_BYTES  (SMEM_FLOATS*4 + 32)   // + 3 mbarriers

// scratch (device globals: allocation-free)
__device__ float g_gx[(size_t)T_ * B_ * H3_];   // [t][b][3H] precomputed x@Wx+bx
__device__ float g_hT[3 * B_ * H_];             // final hidden state

// ---------------------------------------------------------------- helpers
static __device__ __forceinline__ uint32_t s2u(const void* p) {
    uint32_t a;
    asm("{ .reg .u64 t; cvta.to.shared.u64 t, %1; cvt.u32.u64 %0, t; }"
        : "=r"(a) : "l"(p));
    return a;
}
static __device__ __forceinline__ void mbar_init(uint32_t m, int cnt) {
    asm volatile("mbarrier.init.shared.b64 [%0], %1;" :: "r"(m), "r"(cnt) : "memory");
}
static __device__ __forceinline__ void mbar_expect(uint32_t m, uint32_t bytes) {
    asm volatile("mbarrier.arrive.expect_tx.shared.b64 _, [%0], %1;"
                 :: "r"(m), "r"(bytes) : "memory");
}
static __device__ __forceinline__ void mbar_wait(uint32_t m, int ph) {
    asm volatile(
        "{\n\t"
        ".reg .pred P;\n\t"
        "WL%=:\n\t"
        "mbarrier.try_wait.parity.acquire.cta.shared::cta.b64 P, [%0], %1;\n\t"
        "@P bra WD%=;\n\t"
        "bra WL%=;\n\t"
        "WD%=:\n\t"
        "}"
        :: "r"(m), "r"(ph) : "memory");
}
static __device__ __forceinline__ void bulk_g2s(uint32_t dst, const void* src,
                                                uint32_t bytes, uint32_t m) {
    asm volatile(
        "cp.async.bulk.shared::cluster.global.mbarrier::complete_tx::bytes [%0], [%1], %2, [%3];"
        :: "r"(dst), "l"(src), "r"(bytes), "r"(m) : "memory");
}
static __device__ __forceinline__ void fence_async() {
    asm volatile("fence.proxy.async.shared::cta;" ::: "memory");
}
// packed fp32x2 ops
static __device__ __forceinline__ uint64_t pack2(float v) {
    uint64_t r;
    asm("mov.b64 %0, {%1, %1};" : "=l"(r) : "f"(v));
    return r;
}
static __device__ __forceinline__ void fma2(uint64_t& d, uint64_t a, uint64_t b) {
    asm("fma.rn.f32x2 %0, %1, %2, %0;" : "+l"(d) : "l"(a), "l"(b));
}
static __device__ __forceinline__ float f32x2_lo(uint64_t v) {
    return __uint_as_float((uint32_t)v);
}
static __device__ __forceinline__ float f32x2_hi(uint64_t v) {
    return __uint_as_float((uint32_t)(v >> 32));
}
static __device__ __forceinline__ float sigmoidf_(float x) {
    return __fdividef(1.0f, 1.0f + __expf(-x));
}
static __device__ __forceinline__ float tanhf_(float x) {
    float ax = fabsf(x);
    float t  = __expf(-2.0f * ax);
    float r  = __fdividef(1.0f - t, 1.0f + t);
    return x >= 0.0f ? r : -r;
}

// ---------------------------------------------------------------- gx = x @ Wx + bx  (FFMA2)
// M = T*B = 32768 rows (m = t*256 + b), N = 768, K = 128. 64x64 tile, 4x4 micro, row-pair packed.
__global__ void __launch_bounds__(256) k_gx(const float* __restrict__ x,
                                            const float* __restrict__ Wx,
                                            const float* __restrict__ bx) {
    __shared__ float As[16 * 66];   // stride 66: 8B-aligned row pairs, conflict-free stores
    __shared__ float Bs[16 * 64];
    const int tid = threadIdx.x;
    const int tx = tid & 15, ty = tid >> 4;
    const int n0 = blockIdx.x * 64;
    const int m0 = blockIdx.y * 64;

    uint64_t acc2[2][4];
#pragma unroll
    for (int p = 0; p < 2; p++)
#pragma unroll
        for (int c = 0; c < 4; c++) acc2[p][c] = 0ULL;

    for (int k0 = 0; k0 < IN_; k0 += 16) {
#pragma unroll
        for (int i = 0; i < 4; i++) {
            int e  = tid + i * 256;
            int mm = e >> 4, kk = e & 15;
            int m  = m0 + mm;
            int tt = m >> 8, bb = m & 255;
            As[kk * 66 + mm] = x[bb * (T_ * IN_) + tt * IN_ + k0 + kk];
        }
#pragma unroll
        for (int i = 0; i < 4; i++) {
            int e  = tid + i * 256;
            int kk = e >> 6, nn = e & 63;
            Bs[kk * 64 + nn] = Wx[(k0 + kk) * H3_ + n0 + nn];
        }
        __syncthreads();
#pragma unroll
        for (int kk = 0; kk < 16; kk++) {
            uint64_t a01 = *(const uint64_t*)&As[kk * 66 + ty * 4];
            uint64_t a23 = *(const uint64_t*)&As[kk * 66 + ty * 4 + 2];
            float4 b4 = *(const float4*)&Bs[kk * 64 + tx * 4];
            uint64_t p0 = pack2(b4.x), p1 = pack2(b4.y);
            uint64_t p2 = pack2(b4.z), p3 = pack2(b4.w);
            fma2(acc2[0][0], a01, p0); fma2(acc2[0][1], a01, p1);
            fma2(acc2[0][2], a01, p2); fma2(acc2[0][3], a01, p3);
            fma2(acc2[1][0], a23, p0); fma2(acc2[1][1], a23, p1);
            fma2(acc2[1][2], a23, p2); fma2(acc2[1][3], a23, p3);
        }
        __syncthreads();
    }
    float4 bxv = *(const float4*)&bx[n0 + tx * 4];
#pragma unroll
    for (int p = 0; p < 2; p++) {
        float4 lo4, hi4;
        lo4.x = f32x2_lo(acc2[p][0]) + bxv.x;  hi4.x = f32x2_hi(acc2[p][0]) + bxv.x;
        lo4.y = f32x2_lo(acc2[p][1]) + bxv.y;  hi4.y = f32x2_hi(acc2[p][1]) + bxv.y;
        lo4.z = f32x2_lo(acc2[p][2]) + bxv.z;  hi4.z = f32x2_hi(acc2[p][2]) + bxv.z;
        lo4.w = f32x2_lo(acc2[p][3]) + bxv.w;  hi4.w = f32x2_hi(acc2[p][3]) + bxv.w;
        *(float4*)&g_gx[(size_t)(m0 + ty * 4 + 2 * p)     * H3_ + n0 + tx * 4] = lo4;
        *(float4*)&g_gx[(size_t)(m0 + ty * 4 + 2 * p + 1) * H3_ + n0 + tx * 4] = hi4;
    }
}

// ---------------------------------------------------------------- persistent CRU recurrence
// Block owns 8 consecutive (c,b) rows; h state lives in SMEM (transposed, row-pair packed).
// Thread j owns gate-triplet columns {j, j+256, j+512} -> gates computed fully in registers.
// Per step: gh = h @ Wh via fma.rn.f32x2 (Wh streamed from L2 via cp.async.bulk, 2-deep),
// gx tile for the step prefetched into SMEM via TMA under the GEMM.
__global__ void __launch_bounds__(PTH) k_cru(const float* __restrict__ h0,
                                             const float* __restrict__ Wh,
                                             const float* __restrict__ bh) {
    extern __shared__ float sm[];
    float* hst = sm;                               // [256][HSTR] h transposed (pairs packed)
    float* Bs  = sm + HST_FLOATS;                  // [2][32][768] Wh chunk double buffer
    float* gxs = sm + HST_FLOATS + BS_FLOATS;      // [8][768] gx tile for current step
    uint64_t* mb = (uint64_t*)(sm + SMEM_FLOATS);

    const int tid    = threadIdx.x;                // = column j (0..255)
    const int r0     = blockIdx.x * ROWS;
    const int b_base = r0 & (B_ - 1);
    const uint32_t mb0 = s2u(mb), mb1 = s2u(mb + 1), mb2 = s2u(mb + 2);
    const uint32_t bsu0 = s2u(Bs), bsu1 = s2u(Bs + KC * H3_);
    const uint32_t gxsu = s2u(gxs);

    // load initial h: h0[(r0+r)*H + k] -> hst[k*HSTR + r]
    for (int idx = tid; idx < ROWS * H_; idx += PTH)
        hst[(idx & (H_ - 1)) * HSTR + (idx >> 8)] = h0[r0 * H_ + idx];

    uint64_t bh2[3];
#pragma unroll
    for (int g = 0; g < 3; g++) bh2[g] = pack2(bh[g * H_ + tid]);

    if (tid == 0) {
        mbar_init(mb0, 1);
        mbar_init(mb1, 1);
        mbar_init(mb2, 1);
        fence_async();
    }
    __syncthreads();

    if (tid == 0) {
        mbar_expect(mb0, CHUNK_BYTES);
        bulk_g2s(bsu0, Wh, CHUNK_BYTES, mb0);
        mbar_expect(mb1, CHUNK_BYTES);
        bulk_g2s(bsu1, Wh + KC * H3_, CHUNK_BYTES, mb1);
    }

    int ph0 = 0, ph1 = 0, ph2 = 0;
    int cc = 0;
    const int CCMAX = NCHUNK * T_;

    for (int t = 0; t < T_; t++) {
        // prefetch this step's gx tile (consumed in the epilogue, hidden under GEMM)
        if (tid == 0) {
            mbar_expect(mb2, GX_BYTES);
            bulk_g2s(gxsu, g_gx + (size_t)t * (B_ * H3_) + (size_t)b_base * H3_,
                     GX_BYTES, mb2);
        }

        uint64_t acc[4][3];
#pragma unroll
        for (int rp = 0; rp < 4; rp++)
#pragma unroll
            for (int g = 0; g < 3; g++) acc[rp][g] = bh2[g];

        for (int chunk = 0; chunk < NCHUNK; chunk++) {
            const int buf = cc & 1;
            if (buf == 0) { mbar_wait(mb0, ph0); ph0 ^= 1; }
            else          { mbar_wait(mb1, ph1); ph1 ^= 1; }

            const float* bp = Bs + buf * (KC * H3_);
            const float* hp = hst + chunk * (KC * HSTR);
#pragma unroll
            for (int kk = 0; kk < KC; kk++) {
                uint64_t a01 = *(const uint64_t*)(hp + kk * HSTR + 0);
                uint64_t a23 = *(const uint64_t*)(hp + kk * HSTR + 2);
                uint64_t a45 = *(const uint64_t*)(hp + kk * HSTR + 4);
                uint64_t a67 = *(const uint64_t*)(hp + kk * HSTR + 6);
                uint64_t p0 = pack2(bp[kk * H3_ + tid]);
                uint64_t p1 = pack2(bp[kk * H3_ + H_ + tid]);
                uint64_t p2 = pack2(bp[kk * H3_ + 2 * H_ + tid]);
                fma2(acc[0][0], a01, p0); fma2(acc[0][1], a01, p1); fma2(acc[0][2], a01, p2);
                fma2(acc[1][0], a23, p0); fma2(acc[1][1], a23, p1); fma2(acc[1][2], a23, p2);
                fma2(acc[2][0], a45, p0); fma2(acc[2][1], a45, p1); fma2(acc[2][2], a45, p2);
                fma2(acc[3][0], a67, p0); fma2(acc[3][1], a67, p1); fma2(acc[3][2], a67, p2);
            }
            __syncthreads();   // all consumers done with this buffer
            if (tid == 0 && cc + 2 < CCMAX) {
                const int nch = (chunk + 2) & (NCHUNK - 1);
                const uint32_t m = buf ? mb1 : mb0;
                mbar_expect(m, CHUNK_BYTES);
                bulk_g2s(buf ? bsu1 : bsu0, Wh + nch * (KC * H3_), CHUNK_BYTES, m);
            }
            cc++;
        }

        // gate epilogue — fully register-resident per column j
        mbar_wait(mb2, ph2); ph2 ^= 1;
#pragma unroll
        for (int r = 0; r < ROWS; r++) {
            const int rp = r >> 1;
            const bool hi = r & 1;
            const float hr = hi ? f32x2_hi(acc[rp][0]) : f32x2_lo(acc[rp][0]);
            const float hz = hi ? f32x2_hi(acc[rp][1]) : f32x2_lo(acc[rp][1]);
            const float hn = hi ? f32x2_hi(acc[rp][2]) : f32x2_lo(acc[rp][2]);
            const float xr = gxs[r * H3_ + tid];
            const float xz = gxs[r * H3_ + H_ + tid];
            const float xn = gxs[r * H3_ + 2 * H_ + tid];
            const float rg = sigmoidf_(xr + hr);
            const float zg = sigmoidf_(xz + hz);
            const float ng = tanhf_(xn + rg * hn);
            const float ho = hst[tid * HSTR + r];
            hst[tid * HSTR + r] = ng + zg * (ho - ng);
        }
        __syncthreads();
    }

    for (int idx = tid; idx < ROWS * H_; idx += PTH)
        g_hT[r0 * H_ + idx] = hst[(idx & (H_ - 1)) * HSTR + (idx >> 8)];
}

// ---------------------------------------------------------------- out = elu((sum_c hT) @ Wf + bf)
__global__ void __launch_bounds__(128) k_out(const float* __restrict__ Wf,
                                             const float* __restrict__ bf,
                                             float* __restrict__ out) {
    __shared__ float s[H_];
    const int b = blockIdx.x;
    const int tid = threadIdx.x;
    for (int k = tid; k < H_; k += 128)
        s[k] = g_hT[b * H_ + k] + g_hT[B_ * H_ + b * H_ + k] + g_hT[2 * B_ * H_ + b * H_ + k];
    __syncthreads();
    float acc = bf[tid];
#pragma unroll 8
    for (int k = 0; k < H_; k++)
        acc = fmaf(s[k], Wf[k * OUT_ + tid], acc);
    out[b * OUT_ + tid] = acc > 0.0f ? acc : expm1f(acc);
}

// ---------------------------------------------------------------- feature = mean_b hT -> (3, H)
// 24 blocks x 256 threads: warp-row ty sums a 32-batch slice, deterministic smem tree.
__global__ void __launch_bounds__(256) k_feat(float* __restrict__ feat) {
    __shared__ float p[8][32];
    const int tx = threadIdx.x & 31, ty = threadIdx.x >> 5;
    const int jg = blockIdx.x * 32 + tx;            // 0..767
    const int c = jg >> 8, j = jg & 255;
    float s = 0.0f;
#pragma unroll 8
    for (int i = 0; i < 32; i++) {
        const int b = ty * 32 + i;
        s += g_hT[c * (B_ * H_) + b * H_ + j];
    }
    p[ty][tx] = s;
    __syncthreads();
    if (ty == 0) {
        float acc = 0.0f;
#pragma unroll
        for (int q = 0; q < 8; q++) acc += p[q][tx];
        feat[jg] = acc * (1.0f / 256.0f);
    }
}

// ---------------------------------------------------------------- launch
extern "C" void kernel_launch(void* const* d_in, const int* in_sizes, int n_in,
                              void* d_out, int out_size) {
    const float* x  = (const float*)d_in[0];
    const float* h0 = (const float*)d_in[1];
    const float* Wx = (const float*)d_in[2];
    const float* bx = (const float*)d_in[3];
    const float* Wh = (const float*)d_in[4];
    const float* bh = (const float*)d_in[5];
    const float* Wf = (const float*)d_in[6];
    const float* bf = (const float*)d_in[7];
    float* out = (float*)d_out;

    cudaFuncSetAttribute(k_cru, cudaFuncAttributeMaxDynamicSharedMemorySize, SMEM_BYTES);

    dim3 g1(H3_ / 64, (T_ * B_) / 64);   // (12, 512)
    k_gx<<<g1, 256>>>(x, Wx, bx);
    k_cru<<<NBLK, PTH, SMEM_BYTES>>>(h0, Wh, bh);
    k_out<<<B_, 128>>>(Wf, bf, out);
    k_feat<<<24, 256>>>(out + (out_size - 3 * H_));
}

// round 7
// speedup vs baseline: 1.1833x; 1.1833x over previous
#include <cuda_runtime.h>
#include <cstdint>

#define B_   256
#define T_   128
#define IN_  128
#define H_   256
#define H3_  768
#define OUT_ 128

// ---- persistent recurrence config: 64 clusters x 2 CTAs, 12 rows per cluster
#define RWS  12                    // (c,b) state rows per cluster
#define NBLK 128                   // CTAs (64 clusters of 2)
#define PTH  256                   // wg = tid>>7 owns rows 6wg..6wg+5; j = tid&127
#define NCOL 384                   // gate columns per CTA (3 segments of 128)
#define KC   32                    // k rows of Wh per chunk
#define NCHUNK (H_/KC)             // 8
#define NBUF 3
#define CHUNK_BYTES (KC*NCOL*4)    // 49152
#define GX_BYTES (RWS*NCOL*4)      // 18432
#define HSTR 14                    // hst column stride (12 rows + pad, even)
#define HST_FLOATS (H_*HSTR)       // 3584
#define BS_FLOATS  (NBUF*KC*NCOL)  // 36864
#define GXS_FLOATS (RWS*NCOL)      // 4608
#define SMEM_FLOATS (2*HST_FLOATS + BS_FLOATS + GXS_FLOATS)   // 48640
#define SMEM_BYTES  (SMEM_FLOATS*4 + 64)

#define WH2_HALF (H_*NCOL)         // 98304 floats per half
#define GX2_HALF ((size_t)T_*B_*NCOL)  // 12.58M floats per half

// scratch (device globals: allocation-free)
__device__ float g_Wh2[2 * WH2_HALF];            // [q][k][s*128+l] reordered Wh
__device__ float g_gx2[2 * GX2_HALF];            // [q][t*256+b][384] x@Wx+bx, per-half cols
__device__ float g_hT[3 * B_ * H_];              // final hidden state

// ---------------------------------------------------------------- helpers
static __device__ __forceinline__ uint32_t s2u(const void* p) {
    uint32_t a;
    asm("{ .reg .u64 t; cvta.to.shared.u64 t, %1; cvt.u32.u64 %0, t; }"
        : "=r"(a) : "l"(p));
    return a;
}
static __device__ __forceinline__ void mbar_init(uint32_t m, int cnt) {
    asm volatile("mbarrier.init.shared.b64 [%0], %1;" :: "r"(m), "r"(cnt) : "memory");
}
static __device__ __forceinline__ void mbar_expect(uint32_t m, uint32_t bytes) {
    asm volatile("mbarrier.arrive.expect_tx.shared.b64 _, [%0], %1;"
                 :: "r"(m), "r"(bytes) : "memory");
}
static __device__ __forceinline__ void mbar_wait(uint32_t m, int ph) {
    asm volatile(
        "{\n\t"
        ".reg .pred P;\n\t"
        "WL%=:\n\t"
        "mbarrier.try_wait.parity.acquire.cta.shared::cta.b64 P, [%0], %1;\n\t"
        "@P bra WD%=;\n\t"
        "bra WL%=;\n\t"
        "WD%=:\n\t"
        "}"
        :: "r"(m), "r"(ph) : "memory");
}
static __device__ __forceinline__ void bulk_g2s(uint32_t dst, const void* src,
                                                uint32_t bytes, uint32_t m) {
    asm volatile(
        "cp.async.bulk.shared::cluster.global.mbarrier::complete_tx::bytes [%0], [%1], %2, [%3];"
        :: "r"(dst), "l"(src), "r"(bytes), "r"(m) : "memory");
}
static __device__ __forceinline__ void fence_async() {
    asm volatile("fence.proxy.async.shared::cta;" ::: "memory");
}
static __device__ __forceinline__ uint32_t mapa_u32(uint32_t addr, uint32_t rank) {
    uint32_t r;
    asm("mapa.shared::cluster.u32 %0, %1, %2;" : "=r"(r) : "r"(addr), "r"(rank));
    return r;
}
static __device__ __forceinline__ void st_cluster_b64(uint32_t addr, uint64_t v) {
    asm volatile("st.shared::cluster.b64 [%0], %1;" :: "r"(addr), "l"(v) : "memory");
}
#define CLUSTER_ARRIVE() asm volatile("barrier.cluster.arrive.aligned;" ::: "memory")
#define CLUSTER_WAIT()   asm volatile("barrier.cluster.wait.aligned;"   ::: "memory")

// packed fp32x2 ops
static __device__ __forceinline__ uint64_t pack2(float v) {
    uint64_t r;
    asm("mov.b64 %0, {%1, %1};" : "=l"(r) : "f"(v));
    return r;
}
static __device__ __forceinline__ uint64_t pack2f(float lo, float hi) {
    uint64_t r;
    asm("mov.b64 %0, {%1, %2};" : "=l"(r) : "f"(lo), "f"(hi));
    return r;
}
static __device__ __forceinline__ void fma2(uint64_t& d, uint64_t a, uint64_t b) {
    asm("fma.rn.f32x2 %0, %1, %2, %0;" : "+l"(d) : "l"(a), "l"(b));
}
static __device__ __forceinline__ float f32x2_lo(uint64_t v) {
    return __uint_as_float((uint32_t)v);
}
static __device__ __forceinline__ float f32x2_hi(uint64_t v) {
    return __uint_as_float((uint32_t)(v >> 32));
}
static __device__ __forceinline__ float sigmoidf_(float x) {
    return __fdividef(1.0f, 1.0f + __expf(-x));
}
static __device__ __forceinline__ float tanhf_(float x) {
    float ax = fabsf(x);
    float t  = __expf(-2.0f * ax);
    float r  = __fdividef(1.0f - t, 1.0f + t);
    return x >= 0.0f ? r : -r;
}

// ---------------------------------------------------------------- Wh reorder
// g_Wh2[q][k][s*128+l] = Wh[k][s*256 + q*128 + l]
__global__ void __launch_bounds__(256) k_prep(const float* __restrict__ Wh) {
    const int q = blockIdx.y;
    const int e = blockIdx.x * 256 + threadIdx.x;    // 0..98303
    const int k = e / NCOL;
    const int rem = e - k * NCOL;
    const int s = rem >> 7, l = rem & 127;
    g_Wh2[q * WH2_HALF + e] = Wh[k * H3_ + s * 256 + q * 128 + l];
}

// ---------------------------------------------------------------- gx = x @ Wx + bx  (FFMA2)
// Output written per-half: g_gx2[q][m][ s*128 + (n&127) ], m = t*256+b.
__global__ void __launch_bounds__(256) k_gx(const float* __restrict__ x,
                                            const float* __restrict__ Wx,
                                            const float* __restrict__ bx) {
    __shared__ float As[16 * 66];
    __shared__ float Bs[16 * 64];
    const int tid = threadIdx.x;
    const int tx = tid & 15, ty = tid >> 4;
    const int n0 = blockIdx.x * 64;
    const int m0 = blockIdx.y * 64;

    uint64_t acc2[2][4];
#pragma unroll
    for (int p = 0; p < 2; p++)
#pragma unroll
        for (int c = 0; c < 4; c++) acc2[p][c] = 0ULL;

    for (int k0 = 0; k0 < IN_; k0 += 16) {
#pragma unroll
        for (int i = 0; i < 4; i++) {
            int e  = tid + i * 256;
            int mm = e >> 4, kk = e & 15;
            int m  = m0 + mm;
            int tt = m >> 8, bb = m & 255;
            As[kk * 66 + mm] = x[bb * (T_ * IN_) + tt * IN_ + k0 + kk];
        }
#pragma unroll
        for (int i = 0; i < 4; i++) {
            int e  = tid + i * 256;
            int kk = e >> 6, nn = e & 63;
            Bs[kk * 64 + nn] = Wx[(k0 + kk) * H3_ + n0 + nn];
        }
        __syncthreads();
#pragma unroll
        for (int kk = 0; kk < 16; kk++) {
            uint64_t a01 = *(const uint64_t*)&As[kk * 66 + ty * 4];
            uint64_t a23 = *(const uint64_t*)&As[kk * 66 + ty * 4 + 2];
            float4 b4 = *(const float4*)&Bs[kk * 64 + tx * 4];
            uint64_t p0 = pack2(b4.x), p1 = pack2(b4.y);
            uint64_t p2 = pack2(b4.z), p3 = pack2(b4.w);
            fma2(acc2[0][0], a01, p0); fma2(acc2[0][1], a01, p1);
            fma2(acc2[0][2], a01, p2); fma2(acc2[0][3], a01, p3);
            fma2(acc2[1][0], a23, p0); fma2(acc2[1][1], a23, p1);
            fma2(acc2[1][2], a23, p2); fma2(acc2[1][3], a23, p3);
        }
        __syncthreads();
    }
    const int n = n0 + tx * 4;                 // global col; all 4 in same (s,q) block
    const int q = (n >> 7) & 1;
    const int c384 = (n >> 8) * 128 + (n & 127);
    float4 bxv = *(const float4*)&bx[n];
    float* dst = g_gx2 + (size_t)q * GX2_HALF + c384;
#pragma unroll
    for (int p = 0; p < 2; p++) {
        float4 lo4, hi4;
        lo4.x = f32x2_lo(acc2[p][0]) + bxv.x;  hi4.x = f32x2_hi(acc2[p][0]) + bxv.x;
        lo4.y = f32x2_lo(acc2[p][1]) + bxv.y;  hi4.y = f32x2_hi(acc2[p][1]) + bxv.y;
        lo4.z = f32x2_lo(acc2[p][2]) + bxv.z;  hi4.z = f32x2_hi(acc2[p][2]) + bxv.z;
        lo4.w = f32x2_lo(acc2[p][3]) + bxv.w;  hi4.w = f32x2_hi(acc2[p][3]) + bxv.w;
        *(float4*)(dst + (size_t)(m0 + ty * 4 + 2 * p)     * NCOL) = lo4;
        *(float4*)(dst + (size_t)(m0 + ty * 4 + 2 * p + 1) * NCOL) = hi4;
    }
}

// ---------------------------------------------------------------- persistent CRU recurrence
// 64 clusters of 2 CTAs. Cluster owns 12 (c,b) rows; CTA q owns gate-triplet cols
// {j, j+256, j+512}, j in [128q, 128q+128). h state double-buffered in SMEM,
// halves exchanged via DSMEM each step; one cluster barrier per step.
__global__ void __launch_bounds__(PTH) __cluster_dims__(2, 1, 1)
k_cru(const float* __restrict__ h0, const float* __restrict__ bh) {
    extern __shared__ float sm[];
    float* hst0 = sm;                                   // [256][HSTR] h (buffer 0)
    float* hst1 = sm + HST_FLOATS;                      // [256][HSTR] h (buffer 1)
    float* Bs   = sm + 2 * HST_FLOATS;                  // [NBUF][KC][384] Wh chunks
    float* gxs  = sm + 2 * HST_FLOATS + BS_FLOATS;      // [12][384] gx tile
    uint64_t* mb = (uint64_t*)(sm + SMEM_FLOATS);       // 3 Wh + 1 gx barriers

    const int tid = threadIdx.x;
    const int wg  = tid >> 7;           // 0/1 -> rows 6wg..6wg+5
    const int j   = tid & 127;
    const int q   = blockIdx.x & 1;     // cluster rank
    const int r0  = (blockIdx.x >> 1) * RWS;
    const int b_base = r0 & (B_ - 1);
    const int jh  = q * 128 + j;        // owned h column

    uint32_t mbw[NBUF], mbg;
#pragma unroll
    for (int i = 0; i < NBUF; i++) mbw[i] = s2u(mb + i);
    mbg = s2u(mb + NBUF);
    const uint32_t bsu  = s2u(Bs);
    const uint32_t gxsu = s2u(gxs);
    const uint32_t h0u  = s2u(hst0);
    const uint32_t h1u  = s2u(hst1);
    const uint32_t peer_h0 = mapa_u32(h0u, q ^ 1);
    const uint32_t peer_h1 = mapa_u32(h1u, q ^ 1);
    const float* whq = g_Wh2 + q * WH2_HALF;

    // initial h: full 12x256 tile into hst0 (transposed): hst0[k*HSTR + r]
    for (int idx = tid; idx < RWS * H_; idx += PTH) {
        const int r = idx / H_, k = idx - r * H_;
        hst0[k * HSTR + r] = h0[(r0 + r) * H_ + k];
    }

    uint64_t bh2[3];
#pragma unroll
    for (int g = 0; g < 3; g++) bh2[g] = pack2(bh[g * H_ + jh]);

    if (tid == 0) {
#pragma unroll
        for (int i = 0; i < NBUF; i++) mbar_init(mbw[i], 1);
        mbar_init(mbg, 1);
        fence_async();
    }
    __syncthreads();

    // prologue: 3 Wh chunks + gx(t=0)
    if (tid == 0) {
#pragma unroll
        for (int i = 0; i < NBUF; i++) {
            mbar_expect(mbw[i], CHUNK_BYTES);
            bulk_g2s(bsu + i * CHUNK_BYTES, whq + i * (KC * NCOL), CHUNK_BYTES, mbw[i]);
        }
        const int n1 = (b_base + RWS > B_) ? (B_ - b_base) : RWS;
        mbar_expect(mbg, GX_BYTES);
        bulk_g2s(gxsu, g_gx2 + (size_t)q * GX2_HALF + (size_t)b_base * NCOL,
                 n1 * NCOL * 4, mbg);
        if (n1 < RWS)
            bulk_g2s(gxsu + n1 * NCOL * 4, g_gx2 + (size_t)q * GX2_HALF,
                     (RWS - n1) * NCOL * 4, mbg);
    }

    int phw[NBUF] = {0, 0, 0};
    int phg = 0;
    int cc = 0;
    const int CCMAX = NCHUNK * T_;

    for (int t = 0; t < T_; t++) {
        const float* hcur = (t & 1) ? hst1 : hst0;
        const uint32_t hn_loc  = (t & 1) ? h0u : h1u;
        const uint32_t hn_peer = (t & 1) ? peer_h0 : peer_h1;

        uint64_t acc[3][3];
#pragma unroll
        for (int p = 0; p < 3; p++)
#pragma unroll
            for (int g = 0; g < 3; g++) acc[p][g] = bh2[g];

        for (int chunk = 0; chunk < NCHUNK; chunk++) {
            const int buf = cc % NBUF;
            mbar_wait(mbw[buf], phw[buf]);
            phw[buf] ^= 1;

            const float* bp = Bs + buf * (KC * NCOL);
            const float* hp = hcur + chunk * (KC * HSTR) + 6 * wg;
#pragma unroll
            for (int kk = 0; kk < KC; kk++) {
                uint64_t a01 = *(const uint64_t*)(hp + kk * HSTR + 0);
                uint64_t a23 = *(const uint64_t*)(hp + kk * HSTR + 2);
                uint64_t a45 = *(const uint64_t*)(hp + kk * HSTR + 4);
                uint64_t p0 = pack2(bp[kk * NCOL + j]);
                uint64_t p1 = pack2(bp[kk * NCOL + 128 + j]);
                uint64_t p2 = pack2(bp[kk * NCOL + 256 + j]);
                fma2(acc[0][0], a01, p0); fma2(acc[0][1], a01, p1); fma2(acc[0][2], a01, p2);
                fma2(acc[1][0], a23, p0); fma2(acc[1][1], a23, p1); fma2(acc[1][2], a23, p2);
                fma2(acc[2][0], a45, p0); fma2(acc[2][1], a45, p1); fma2(acc[2][2], a45, p2);
            }
            __syncthreads();   // buffer free for reuse
            if (tid == 0 && cc + NBUF < CCMAX) {
                const int g = cc + NBUF;
                const int nch = g & (NCHUNK - 1);
                const uint32_t m = mbw[buf];
                mbar_expect(m, CHUNK_BYTES);
                bulk_g2s(bsu + buf * CHUNK_BYTES, whq + nch * (KC * NCOL), CHUNK_BYTES, m);
            }
            cc++;
        }

        // gate epilogue — register-resident, write h(next) locally and to peer
        mbar_wait(mbg, phg); phg ^= 1;
#pragma unroll
        for (int p = 0; p < 3; p++) {
            float nv[2];
#pragma unroll
            for (int hi = 0; hi < 2; hi++) {
                const int r = 6 * wg + 2 * p + hi;
                const float hr = hi ? f32x2_hi(acc[p][0]) : f32x2_lo(acc[p][0]);
                const float hz = hi ? f32x2_hi(acc[p][1]) : f32x2_lo(acc[p][1]);
                const float hn = hi ? f32x2_hi(acc[p][2]) : f32x2_lo(acc[p][2]);
                const float xr = gxs[r * NCOL + j];
                const float xz = gxs[r * NCOL + 128 + j];
                const float xn = gxs[r * NCOL + 256 + j];
                const float rg = sigmoidf_(xr + hr);
                const float zg = sigmoidf_(xz + hz);
                const float ng = tanhf_(xn + rg * hn);
                const float ho = hcur[jh * HSTR + r];
                nv[hi] = ng + zg * (ho - ng);
            }
            const uint64_t pr = pack2f(nv[0], nv[1]);
            const uint32_t off = (uint32_t)(jh * HSTR + 6 * wg + 2 * p) * 4u;
            *(uint64_t*)((char*)sm + (hn_loc - s2u(sm)) + off) = pr;  // local store
            st_cluster_b64(hn_peer + off, pr);                        // peer store
        }

        // one cluster barrier per step: orders local+peer h writes before next GEMM,
        // and gxs consumption before the next gx prefetch.
        CLUSTER_ARRIVE();
        CLUSTER_WAIT();

        if (tid == 0 && t + 1 < T_) {
            const int n1 = (b_base + RWS > B_) ? (B_ - b_base) : RWS;
            mbar_expect(mbg, GX_BYTES);
            bulk_g2s(gxsu, g_gx2 + (size_t)q * GX2_HALF +
                     ((size_t)(t + 1) * B_ + b_base) * NCOL, n1 * NCOL * 4, mbg);
            if (n1 < RWS)
                bulk_g2s(gxsu + n1 * NCOL * 4,
                         g_gx2 + (size_t)q * GX2_HALF + (size_t)(t + 1) * B_ * NCOL,
                         (RWS - n1) * NCOL * 4, mbg);
        }
    }

    // final h (T even -> lives in hst0); each CTA stores its own column half
    for (int idx = tid; idx < RWS * 128; idx += PTH) {
        const int r = idx >> 7, l = idx & 127;
        g_hT[(r0 + r) * H_ + q * 128 + l] = hst0[(q * 128 + l) * HSTR + r];
    }
}

// ---------------------------------------------------------------- out = elu((sum_c hT) @ Wf + bf)
__global__ void __launch_bounds__(128) k_out(const float* __restrict__ Wf,
                                             const float* __restrict__ bf,
                                             float* __restrict__ out) {
    __shared__ float s[H_];
    const int b = blockIdx.x;
    const int tid = threadIdx.x;
    for (int k = tid; k < H_; k += 128)
        s[k] = g_hT[b * H_ + k] + g_hT[B_ * H_ + b * H_ + k] + g_hT[2 * B_ * H_ + b * H_ + k];
    __syncthreads();
    float acc = bf[tid];
#pragma unroll 8
    for (int k = 0; k < H_; k++)
        acc = fmaf(s[k], Wf[k * OUT_ + tid], acc);
    out[b * OUT_ + tid] = acc > 0.0f ? acc : expm1f(acc);
}

// ---------------------------------------------------------------- feature = mean_b hT -> (3, H)
__global__ void __launch_bounds__(256) k_feat(float* __restrict__ feat) {
    __shared__ float p[8][32];
    const int tx = threadIdx.x & 31, ty = threadIdx.x >> 5;
    const int jg = blockIdx.x * 32 + tx;            // 0..767
    const int c = jg >> 8, j = jg & 255;
    float s = 0.0f;
#pragma unroll 8
    for (int i = 0; i < 32; i++) {
        const int b = ty * 32 + i;
        s += g_hT[c * (B_ * H_) + b * H_ + j];
    }
    p[ty][tx] = s;
    __syncthreads();
    if (ty == 0) {
        float acc = 0.0f;
#pragma unroll
        for (int qq = 0; qq < 8; qq++) acc += p[qq][tx];
        feat[jg] = acc * (1.0f / 256.0f);
    }
}

// ---------------------------------------------------------------- launch
extern "C" void kernel_launch(void* const* d_in, const int* in_sizes, int n_in,
                              void* d_out, int out_size) {
    const float* x  = (const float*)d_in[0];
    const float* h0 = (const float*)d_in[1];
    const float* Wx = (const float*)d_in[2];
    const float* bx = (const float*)d_in[3];
    const float* Wh = (const float*)d_in[4];
    const float* bh = (const float*)d_in[5];
    const float* Wf = (const float*)d_in[6];
    const float* bf = (const float*)d_in[7];
    float* out = (float*)d_out;

    cudaFuncSetAttribute(k_cru, cudaFuncAttributeMaxDynamicSharedMemorySize, SMEM_BYTES);

    dim3 gp(WH2_HALF / 256, 2);          // (384, 2)
    k_prep<<<gp, 256>>>(Wh);
    dim3 g1(H3_ / 64, (T_ * B_) / 64);   // (12, 512)
    k_gx<<<g1, 256>>>(x, Wx, bx);
    k_cru<<<NBLK, PTH, SMEM_BYTES>>>(h0, bh);
    k_out<<<B_, 128>>>(Wf, bf, out);
    k_feat<<<24, 256>>>(out + (out_size - 3 * H_));
}